// round 15
// baseline (speedup 1.0000x reference)
#include <cuda_runtime.h>
#include <cuda_bf16.h>
#include <cstdint>

// ---------------------------------------------------------------------------
// ASDHead v11 — pre-converted weights, lean staging:
//  k_prep : blocks 0-63  = s_proj HMMA (v10 k_sgemm, proven)
//           blocks 64-95 = W_f transpose -> g_Whi/g_Wlo bf16 hi/lo (v7 code)
//  k_main : fused f_proj GEMM + relu-dot, grid 256. B staging = raw uint4
//           copies of pre-converted weights (v7's staging). Single buffer,
//           low regs. Phase B unchanged (LDS.128).
// R14 lesson: double-buffer cost 128 regs for zero gain; in-kernel fp32->bf16
// B splitting was ~10K warp-instrs/SM of avoidable conversion.
// ---------------------------------------------------------------------------

#define D_MODEL 256
#define D_HID   128
#define BATCH   8
#define SEQ     1024
#define NSLOT   64
#define BPAD    72

typedef unsigned long long u64;
typedef unsigned int u32;

__device__ float g_sproj[BATCH * NSLOT * D_HID];             // 256 KB
__device__ __align__(16) __nv_bfloat16 g_Whi[D_HID * 256];   // W_f^T hi [h][k]
__device__ __align__(16) __nv_bfloat16 g_Wlo[D_HID * 256];   // W_f^T lo [h][k]

// -------------------- helpers ----------------------------------------------
__device__ __forceinline__ u64 fma2(u64 a, u64 b, u64 c) {
    u64 d; asm("fma.rn.f32x2 %0, %1, %2, %3;" : "=l"(d) : "l"(a), "l"(b), "l"(c));
    return d;
}
__device__ __forceinline__ u64 add2(u64 a, u64 b) {
    u64 d; asm("add.rn.f32x2 %0, %1, %2;" : "=l"(d) : "l"(a), "l"(b));
    return d;
}
__device__ __forceinline__ void unpack2(u64 v, float& lo, float& hi) {
    asm("mov.b64 {%0, %1}, %2;" : "=f"(lo), "=f"(hi) : "l"(v));
}
__device__ __forceinline__ u64 relu2(u64 x) {
    float lo, hi; unpack2(x, lo, hi);
    lo = fmaxf(lo, 0.f); hi = fmaxf(hi, 0.f);
    u64 r; asm("mov.b64 %0, {%1, %2};" : "=l"(r) : "f"(lo), "f"(hi));
    return r;
}
__device__ __forceinline__ u32 cvt_bf16x2(float a, float b) {
    u32 r; asm("cvt.rn.bf16x2.f32 %0, %1, %2;" : "=r"(r) : "f"(b), "f"(a));
    return r;
}
__device__ __forceinline__ void split2(float x, float y, u32& hi, u32& lo) {
    hi = cvt_bf16x2(x, y);
    float hx = __uint_as_float(hi << 16);
    float hy = __uint_as_float(hi & 0xFFFF0000u);
    lo = cvt_bf16x2(x - hx, y - hy);
}
__device__ __forceinline__ void mma16816(float& c0, float& c1, float& c2, float& c3,
                                         u32 a0, u32 a1, u32 a2, u32 a3,
                                         u32 b0, u32 b1) {
    asm volatile(
        "mma.sync.aligned.m16n8k16.row.col.f32.bf16.bf16.f32 "
        "{%0,%1,%2,%3}, {%4,%5,%6,%7}, {%8,%9}, {%0,%1,%2,%3};"
        : "+f"(c0), "+f"(c1), "+f"(c2), "+f"(c3)
        : "r"(a0), "r"(a1), "r"(a2), "r"(a3), "r"(b0), "r"(b1));
}
__device__ __forceinline__ void load_a(const float* __restrict__ arow, int kk,
                                       u32 ah[4], u32 al[4]) {
    float2 p00 = *(const float2*)(arow + kk);
    float2 p10 = *(const float2*)(arow + kk + 8 * D_MODEL);
    float2 p01 = *(const float2*)(arow + kk + 8);
    float2 p11 = *(const float2*)(arow + kk + 8 * D_MODEL + 8);
    split2(p00.x, p00.y, ah[0], al[0]);
    split2(p10.x, p10.y, ah[1], al[1]);
    split2(p01.x, p01.y, ah[2], al[2]);
    split2(p11.x, p11.y, ah[3], al[3]);
}

// -------------------- K_prep: s_proj (0-63) + W_f convert (64-95) -----------
__global__ void __launch_bounds__(256) k_prep(const float* __restrict__ slots,
                                              const float* __restrict__ Wproj,
                                              const float* __restrict__ bproj) {
    int tid = threadIdx.x;
    if (blockIdx.x < 64) {
        // ---- s_proj: v10 k_sgemm body (proven) ----
        __shared__ __align__(16) __nv_bfloat16 Bhi[32 * BPAD];
        __shared__ __align__(16) __nv_bfloat16 Blo[32 * BPAD];
        int wid = tid >> 5, lane = tid & 31;
        int m0 = (blockIdx.x >> 2) * 32, nbase = (blockIdx.x & 3) * 32;
        int mbase = (wid & 1) * 16, ng = wid >> 1;
        const float* arow = slots + (size_t)(m0 + mbase + (lane >> 2)) * D_MODEL
                                  + (lane & 3) * 2;
        float acc[4] = {0.f, 0.f, 0.f, 0.f};
#pragma unroll 1
        for (int kc = 0; kc < 4; kc++) {
            __syncthreads();
            {
                int h = tid & 31, kg = tid >> 5;
                const float* wp = Wproj
                    + (size_t)(256 + kc * 64 + kg * 8) * D_HID + nbase + h;
                u32 hb[4], lb[4];
#pragma unroll
                for (int p = 0; p < 4; p++) {
                    float x0 = wp[(2 * p) * D_HID];
                    float x1 = wp[(2 * p + 1) * D_HID];
                    split2(x0, x1, hb[p], lb[p]);
                }
                *(uint4*)(Bhi + h * BPAD + kg * 8) = make_uint4(hb[0], hb[1], hb[2], hb[3]);
                *(uint4*)(Blo + h * BPAD + kg * 8) = make_uint4(lb[0], lb[1], lb[2], lb[3]);
            }
            __syncthreads();
#pragma unroll
            for (int ks = 0; ks < 4; ks++) {
                u32 ah[4], al[4];
                load_a(arow, kc * 64 + ks * 16, ah, al);
                int nrow = ng * 8 + (lane >> 2);
                int kb = ks * 16 + (lane & 3) * 2;
                u32 bh0 = *(const u32*)(Bhi + nrow * BPAD + kb);
                u32 bh1 = *(const u32*)(Bhi + nrow * BPAD + kb + 8);
                u32 bl0 = *(const u32*)(Blo + nrow * BPAD + kb);
                u32 bl1 = *(const u32*)(Blo + nrow * BPAD + kb + 8);
                mma16816(acc[0], acc[1], acc[2], acc[3], ah[0], ah[1], ah[2], ah[3], bh0, bh1);
                mma16816(acc[0], acc[1], acc[2], acc[3], ah[0], ah[1], ah[2], ah[3], bl0, bl1);
                mma16816(acc[0], acc[1], acc[2], acc[3], al[0], al[1], al[2], al[3], bh0, bh1);
            }
        }
        int r0 = m0 + mbase + (lane >> 2);
        int col = nbase + ng * 8 + (lane & 3) * 2;
        float2 bp = *(const float2*)(bproj + col);
        float2 v0; v0.x = acc[0] + bp.x; v0.y = acc[1] + bp.y;
        float2 v1; v1.x = acc[2] + bp.x; v1.y = acc[3] + bp.y;
        *(float2*)(g_sproj + (size_t)r0 * D_HID + col) = v0;
        *(float2*)(g_sproj + (size_t)(r0 + 8) * D_HID + col) = v1;
    } else {
        // ---- W_f transpose -> bf16 hi/lo [h][k] (v6.1/v7 proven code) ----
        __shared__ float tile[32][33];
        int bid = blockIdx.x - 64;                 // 0..31
        int k0 = (bid & 7) * 32, h0 = (bid >> 3) * 32;
        int r = tid >> 5, c = tid & 31;
#pragma unroll
        for (int i = 0; i < 4; i++) {
            int row = i * 8 + r;
            tile[row][c] = Wproj[(size_t)(k0 + row) * D_HID + h0 + c];
        }
        __syncthreads();
#pragma unroll
        for (int i = 0; i < 4; i++) {
            int row = i * 8 + r;
            float x = tile[c][row];
            __nv_bfloat16 hi = __float2bfloat16_rn(x);
            float lo = x - __bfloat162float(hi);
            g_Whi[(h0 + row) * 256 + k0 + c] = hi;
            g_Wlo[(h0 + row) * 256 + k0 + c] = __float2bfloat16_rn(lo);
        }
    }
}

// -------------------- K_main: fused GEMM + relu-dot -------------------------
// grid 256: b = blk>>5, t0 = (blk&31)*32.  Single B buffer; fsh aliases Bhi.
#define FS 132
#define BT  18432                          // one B tile (hi or lo), bytes
#define SSH_OFF (2 * BT)                   // 36864
#define WSH_OFF (SSH_OFF + 64 * FS * 4)    // 70656
#define MAIN_SMEM (WSH_OFF + 512)          // 71168

extern __shared__ char msm[];

__global__ void __launch_bounds__(256, 2) k_main(const float* __restrict__ features,
                                                 const float* __restrict__ whead,
                                                 const float* __restrict__ bhead,
                                                 float* __restrict__ out) {
    __nv_bfloat16* Bhi = (__nv_bfloat16*)msm;
    __nv_bfloat16* Blo = (__nv_bfloat16*)(msm + BT);
    float* ssh = (float*)(msm + SSH_OFF);          // 64 x 132
    u64*   wsh = (u64*)(msm + WSH_OFF);
    float* fsh = (float*)msm;                      // alias Bhi (16.9K < 18.4K)

    int tid = threadIdx.x, wid = tid >> 5, lane = tid & 31;
    int b = blockIdx.x >> 5, t0 = (blockIdx.x & 31) * 32;
    int mbase = (wid & 1) * 16, n0 = (wid >> 1) * 32;

    // stage s/w early — LDG latency hides under Phase A
#pragma unroll
    for (int i = 0; i < 8; i++) {
        int q = i * 256 + tid;
        int r = q >> 5, c4 = (q & 31) * 4;
        *(float4*)&ssh[r * FS + c4] =
            *(const float4*)(g_sproj + (size_t)(b * NSLOT + r) * D_HID + c4);
    }
    if (tid < 64) wsh[tid] = ((const u64*)whead)[tid];
    float bh = bhead[0];

    const float* arow = features
        + (size_t)(b * SEQ + t0 + mbase + (lane >> 2)) * D_MODEL + (lane & 3) * 2;
    float acc[4][4];
#pragma unroll
    for (int j = 0; j < 4; j++)
#pragma unroll
        for (int q = 0; q < 4; q++) acc[j][q] = 0.f;

#pragma unroll 1
    for (int kc = 0; kc < 4; kc++) {
        if (kc > 0) __syncthreads();               // prev mma done with tiles
        // ---- stage B chunk: pure copies of pre-converted weights ----
        {
            int n = tid >> 1, half = tid & 1;
            const uint4* sh = (const uint4*)(g_Whi + n * 256 + kc * 64 + half * 32);
            const uint4* sl = (const uint4*)(g_Wlo + n * 256 + kc * 64 + half * 32);
            uint4* dh = (uint4*)(Bhi + n * BPAD + half * 32);
            uint4* dl = (uint4*)(Blo + n * BPAD + half * 32);
            dh[0] = sh[0]; dh[1] = sh[1]; dh[2] = sh[2]; dh[3] = sh[3];
            dl[0] = sl[0]; dl[1] = sl[1]; dl[2] = sl[2]; dl[3] = sl[3];
        }
        __syncthreads();

#pragma unroll
        for (int ks = 0; ks < 4; ks++) {
            u32 ah[4], al[4];
            load_a(arow, kc * 64 + ks * 16, ah, al);
            int kb = ks * 16 + (lane & 3) * 2;
#pragma unroll
            for (int j = 0; j < 4; j++) {
                int nrow = n0 + j * 8 + (lane >> 2);
                u32 bh0 = *(const u32*)(Bhi + nrow * BPAD + kb);
                u32 bh1 = *(const u32*)(Bhi + nrow * BPAD + kb + 8);
                u32 bl0 = *(const u32*)(Blo + nrow * BPAD + kb);
                u32 bl1 = *(const u32*)(Blo + nrow * BPAD + kb + 8);
                mma16816(acc[j][0], acc[j][1], acc[j][2], acc[j][3],
                         ah[0], ah[1], ah[2], ah[3], bh0, bh1);
                mma16816(acc[j][0], acc[j][1], acc[j][2], acc[j][3],
                         ah[0], ah[1], ah[2], ah[3], bl0, bl1);
                mma16816(acc[j][0], acc[j][1], acc[j][2], acc[j][3],
                         al[0], al[1], al[2], al[3], bh0, bh1);
            }
        }
    }
    __syncthreads();                               // tiles dead; fsh may alias

    // acc -> fsh
    int mrow = mbase + (lane >> 2);
#pragma unroll
    for (int j = 0; j < 4; j++) {
        int col = n0 + j * 8 + (lane & 3) * 2;
        float2 v0; v0.x = acc[j][0]; v0.y = acc[j][1];
        float2 v1; v1.x = acc[j][2]; v1.y = acc[j][3];
        *(float2*)&fsh[mrow * FS + col] = v0;
        *(float2*)&fsh[(mrow + 8) * FS + col] = v1;
    }
    __syncthreads();

    // ---------------- Phase B: relu-dot, 4t x 2n, LDS.128 ----------------
    int tq = lane >> 2, np = lane & 3;
    int nn = wid * 8 + np * 2;
    const float* fp = fsh + tq * FS;
    const float* sp = ssh + nn * FS;

    u64 bacc[4][2];
#pragma unroll
    for (int i = 0; i < 4; i++) { bacc[i][0] = 0ULL; bacc[i][1] = 0ULL; }

#pragma unroll 4
    for (int h2 = 0; h2 < 32; h2++) {
        ulonglong2 wv  = *(const ulonglong2*)&wsh[2 * h2];
        ulonglong2 sv0 = *(const ulonglong2*)&sp[4 * h2];
        ulonglong2 sv1 = *(const ulonglong2*)&sp[FS + 4 * h2];
#pragma unroll
        for (int i = 0; i < 4; i++) {
            ulonglong2 fv = *(const ulonglong2*)&fp[i * 8 * FS + 4 * h2];
            bacc[i][0] = fma2(relu2(add2(fv.x, sv0.x)), wv.x, bacc[i][0]);
            bacc[i][0] = fma2(relu2(add2(fv.y, sv0.y)), wv.y, bacc[i][0]);
            bacc[i][1] = fma2(relu2(add2(fv.x, sv1.x)), wv.x, bacc[i][1]);
            bacc[i][1] = fma2(relu2(add2(fv.y, sv1.y)), wv.y, bacc[i][1]);
        }
    }

#pragma unroll
    for (int i = 0; i < 4; i++) {
        int t = tq + 8 * i;
        float a, c, d, e;
        unpack2(bacc[i][0], a, c);
        unpack2(bacc[i][1], d, e);
        float2 o; o.x = a + c + bh; o.y = d + e + bh;
        *(float2*)&out[(size_t)(b * SEQ + t0 + t) * NSLOT + nn] = o;
    }
}

// -------------------- launch -----------------------------------------------
extern "C" void kernel_launch(void* const* d_in, const int* in_sizes, int n_in,
                              void* d_out, int out_size) {
    const float* features = (const float*)d_in[0];
    const float* slots    = (const float*)d_in[1];
    const float* W_proj   = (const float*)d_in[2];
    const float* b_proj   = (const float*)d_in[3];
    const float* w_head   = (const float*)d_in[4];
    const float* b_head   = (const float*)d_in[5];
    float* out = (float*)d_out;

    cudaFuncSetAttribute(k_main, cudaFuncAttributeMaxDynamicSharedMemorySize,
                         MAIN_SMEM);

    k_prep<<<96, 256>>>(slots, W_proj, b_proj);
    k_main<<<256, 256, MAIN_SMEM>>>(features, w_head, b_head, out);
}